// round 12
// baseline (speedup 1.0000x reference)
#include <cuda_runtime.h>
#include <math.h>

#define BB 16
#define NN 4096
#define CC 256
#define KK 8
#define SLICES 2
#define QUARTERS 4
#define CHUNK 64
#define EPSF 1e-6f
#define RATIOF 0.1f

#define BN (BB*NN)   /* 65536 tokens */
#define BK (BB*KK)   /* 128 (batch, expert) pairs */

// ---------------- device scratch (no allocations allowed) ----------------
__device__ float  g_gbias[BK];
__device__ int    g_route_e[BN];      // packed e0 | e1<<8
__device__ float2 g_route_w[BN];      // (w0, w1)
__device__ int    g_cnt[KK];
__device__ float  g_confpart[BN/8];
__device__ int    g_listcnt[BK];
__device__ float  g_mass[BK];
__device__ int    g_list_n[BK*NN];
__device__ float  g_list_w[BK*NN];
__device__ float  g_part[BK*SLICES*CC];

// ---------------- tf32 helpers ----------------
__device__ __forceinline__ unsigned f2tf(float f){
    unsigned u; asm("cvt.rna.tf32.f32 %0, %1;" : "=r"(u) : "f"(f)); return u;
}
__device__ __forceinline__ void mma8(float* d, unsigned a0,unsigned a1,unsigned a2,unsigned a3,
                                     unsigned b0,unsigned b1){
    asm volatile("mma.sync.aligned.m16n8k8.row.col.f32.tf32.tf32.f32 "
                 "{%0,%1,%2,%3}, {%4,%5,%6,%7}, {%8,%9}, {%0,%1,%2,%3};"
                 : "+f"(d[0]), "+f"(d[1]), "+f"(d[2]), "+f"(d[3])
                 : "r"(a0),"r"(a1),"r"(a2),"r"(a3),"r"(b0),"r"(b1));
}

// ---------------- K0: zero counters + per-(b,k) gate bias ----------------
__global__ void k0_init(const float* __restrict__ geno, const float* __restrict__ Wgg,
                        const float* __restrict__ bgg, const float* __restrict__ bg){
    int i = threadIdx.x;              // 0..127 == (b,k)
    if (i < KK) g_cnt[i] = 0;
    int b = i / KK, k = i % KK;
    const float* g = geno + b*CC;
    const float* w = Wgg + k*CC;
    float s = 0.f;
    #pragma unroll 8
    for (int j = 0; j < CC; j++) s += g[j]*w[j];
    g_gbias[i] = bg[k] + RATIOF*(s + bgg[k]);
}

// ---------------- K1: gating (1 warp per token) ----------------
__global__ void k1_gate(const float* __restrict__ tokens, const float* __restrict__ Wg){
    int warp = threadIdx.x >> 5, lane = threadIdx.x & 31;
    int idx = blockIdx.x*8 + warp;
    int b = idx >> 12;
    const float* x = tokens + (size_t)idx*CC;

    float acc[KK];
    #pragma unroll
    for (int k = 0; k < KK; k++) acc[k] = 0.f;
    #pragma unroll
    for (int i = 0; i < 8; i++){
        int j = lane + 32*i;
        float xv = x[j];
        #pragma unroll
        for (int k = 0; k < KK; k++) acc[k] = fmaf(xv, Wg[k*CC + j], acc[k]);
    }
    #pragma unroll
    for (int k = 0; k < KK; k++){
        #pragma unroll
        for (int off = 16; off; off >>= 1) acc[k] += __shfl_xor_sync(0xffffffffu, acc[k], off);
    }

    __shared__ int   s_cnt[KK];
    __shared__ float s_conf[8];
    if (threadIdx.x < KK) s_cnt[threadIdx.x] = 0;
    __syncthreads();

    if (lane == 0){
        float v0 = -1e30f, v1 = -1e30f; int i0 = 0, i1 = 0;
        #pragma unroll
        for (int k = 0; k < KK; k++){
            float v = acc[k] + g_gbias[b*KK + k];
            if (v > v0){ v1 = v0; i1 = i0; v0 = v; i0 = k; }
            else if (v > v1){ v1 = v; i1 = k; }
        }
        float e  = expf(v1 - v0);
        float w0 = 1.f/(1.f + e);
        float w1 = e/(1.f + e);
        w0 = fmaxf(w0, EPSF); w1 = fmaxf(w1, EPSF);
        float inv = 1.f/(w0 + w1); w0 *= inv; w1 *= inv;
        g_route_e[idx] = i0 | (i1 << 8);
        g_route_w[idx] = make_float2(w0, w1);
        atomicAdd(&s_cnt[i0], 1);
        atomicAdd(&s_cnt[i1], 1);
        s_conf[warp] = v0 - v1;
    }
    __syncthreads();
    if (threadIdx.x < KK) atomicAdd(&g_cnt[threadIdx.x], s_cnt[threadIdx.x]);
    if (threadIdx.x == 0){
        float c = 0.f;
        #pragma unroll
        for (int w = 0; w < 8; w++) c += s_conf[w];
        g_confpart[blockIdx.x] = c;
    }
}

// ---------------- K2: deterministic compaction per (b,k) ----------------
__global__ void k2_compact(){
    int bk = blockIdx.x, b = bk >> 3, k = bk & 7;
    int tid = threadIdx.x, lane = tid & 31, warp = tid >> 5;
    __shared__ int   s_base, s_wtot[8], s_woff[8];
    __shared__ float s_wsum[8];
    __shared__ float s_mass;
    if (tid == 0){ s_base = 0; s_mass = 0.f; }
    __syncthreads();

    for (int r = 0; r < 16; r++){
        int t   = r*256 + tid;
        int idx = b*NN + t;
        int pe  = g_route_e[idx];
        float2 ww = g_route_w[idx];
        int e0 = pe & 255, e1 = pe >> 8;
        float myw = (e0 == k) ? ww.x : ((e1 == k) ? ww.y : 0.f);
        int pres = (e0 == k) || (e1 == k);

        unsigned ball = __ballot_sync(0xffffffffu, pres);
        int rank = __popc(ball & ((1u << lane) - 1u));
        float wsum = myw;
        #pragma unroll
        for (int off = 16; off; off >>= 1) wsum += __shfl_xor_sync(0xffffffffu, wsum, off);
        if (lane == 0){ s_wtot[warp] = __popc(ball); s_wsum[warp] = wsum; }
        __syncthreads();
        if (tid == 0){
            int o = s_base; float ms = s_mass;
            #pragma unroll
            for (int w = 0; w < 8; w++){ s_woff[w] = o; o += s_wtot[w]; ms += s_wsum[w]; }
            s_base = o; s_mass = ms;
        }
        __syncthreads();
        if (pres){
            int pos = s_woff[warp] + rank;
            g_list_n[bk*NN + pos] = t;
            g_list_w[bk*NN + pos] = myw;
        }
        __syncthreads();
    }
    if (tid == 0){ g_listcnt[bk] = s_base; g_mass[bk] = s_mass; }
}

// ---------------- K3: tf32 mma.sync layer-1 GEMM, 2 blocks/SM ----------------
// Per block: 64-channel QUARTER of W1[k] resident (tf32, pair-interleaved
// columns -> A-frags as conflict-free LDS.64), 64-token chunks streamed in
// two 128-j stages through a SINGLE X buffer (cross-block overlap hides LDG).
// Warp tile m32 x n16 (8 warps = 2 m-groups x 4 n-groups).
// smem words: X[64tok][132] | Ws[64ch][264] | Wl[64]
#define XSTRIDE   132
#define WSTRIDE3  264
#define X_WORDS   (64*XSTRIDE)             /* 8448  */
#define WS_OFF    X_WORDS
#define WS_WORDS  (64*WSTRIDE3)            /* 16896 */
#define WL_OFF    (WS_OFF + WS_WORDS)      /* 25344 */
#define SM_WORDS  (WL_OFF + 64)            /* 25408 words = 101632 B */

__global__ void __launch_bounds__(256, 2)
k3_gemm(const float* __restrict__ tokens, const float* __restrict__ W1, const float* __restrict__ b1){
    extern __shared__ float sm[];
    float* Ws = sm + WS_OFF;
    float* Wl = sm + WL_OFF;

    // blockIdx.x = bk*(QUARTERS*SLICES) + quarter*SLICES + sl
    int bk      = blockIdx.x >> 3;
    int rest    = blockIdx.x & 7;
    int quarter = rest >> 1;
    int sl      = rest & 1;
    int b = bk >> 3, k = bk & 7;

    int cnt = g_listcnt[bk];
    int nchunks = (cnt + CHUNK - 1) / CHUNK;

    int tid = threadIdx.x;
    int lane = tid & 31, wid = tid >> 5;
    int gID = lane >> 2, r = lane & 3;
    int wm = wid & 1, wn = wid >> 1;      // wm: 32-ch group (of 64), wn: 16-token group (of 64)

    if (sl >= nchunks){                   // idle slice
        if (tid < 64) g_part[(size_t)(bk*SLICES + sl)*CC + quarter*64 + tid] = 0.f;
        return;
    }

    // ---- load W1 quarter [64ch][256j] once: tf32-convert + pair-interleave ----
    // per 8-j octet: [j0, j0+4, j0+1, j0+5, j0+2, j0+6, j0+3, j0+7]
    {
        int row = tid >> 2, seg = tid & 3;   // 64 rows x 4 segments of 64 cols
        const float* wsrc = W1 + ((size_t)k*CC + quarter*64 + row)*CC + seg*64;
        float* wdst = Ws + row*WSTRIDE3 + seg*64;
        #pragma unroll
        for (int o = 0; o < 8; o++){
            float4 fa = *(const float4*)(wsrc + o*8);
            float4 fb = *(const float4*)(wsrc + o*8 + 4);
            uint4 u0, u1;
            u0.x=f2tf(fa.x); u0.y=f2tf(fb.x); u0.z=f2tf(fa.y); u0.w=f2tf(fb.y);
            u1.x=f2tf(fa.z); u1.y=f2tf(fb.z); u1.z=f2tf(fa.w); u1.w=f2tf(fb.w);
            *(uint4*)(wdst + o*8)     = u0;
            *(uint4*)(wdst + o*8 + 4) = u1;
        }
    }

    // bias: channels quarter*64 + wm*32 + mt*16 + gID (+8)
    float bias[2][2];
    {
        const float* bp = b1 + k*CC + quarter*64 + wm*32;
        bias[0][0] = bp[gID];      bias[0][1] = bp[gID + 8];
        bias[1][0] = bp[16 + gID]; bias[1][1] = bp[24 + gID];
    }

    float cp[2][2] = {{0.f,0.f},{0.f,0.f}};

    // loader: token ltok (0..63), j-quarter q (32 j of the current 128-j stage)
    int ltok = tid & 63, q = tid >> 6;

    // prologue: chunk sl, row lookup + wl + LDG stage0
    int c = sl;
    const float* xbase;
    float wlv;
    float4 xld[8];
    {
        int tg = c*CHUNK + ltok;
        int n = g_list_n[bk*NN + (tg < cnt ? tg : c*CHUNK)];
        wlv = (tg < cnt) ? g_list_w[bk*NN + tg] : 0.f;
        xbase = tokens + (size_t)(b*NN + n)*CC;
        const float4* xr = (const float4*)(xbase + q*32);
        #pragma unroll
        for (int i = 0; i < 8; i++) xld[i] = xr[i];
    }

    while (1){
        float acc[2][2][4];
        #pragma unroll
        for (int mt=0; mt<2; mt++)
            #pragma unroll
            for (int nt=0; nt<2; nt++)
                #pragma unroll
                for (int i2=0; i2<4; i2++) acc[mt][nt][i2] = 0.f;

        #pragma unroll
        for (int s = 0; s < 2; s++){
            __syncthreads();   // previous compute done reading X (or W-store visible on 1st pass)
            // ---- STS stage s into the single X buffer ----
            {
                float* xd = sm + ltok*XSTRIDE + q*32;
                #pragma unroll
                for (int i = 0; i < 8; i++){
                    uint4 u;
                    u.x=f2tf(xld[i].x); u.y=f2tf(xld[i].y);
                    u.z=f2tf(xld[i].z); u.w=f2tf(xld[i].w);
                    *(uint4*)(xd + i*4) = u;
                }
                if (s == 0 && q == 0) Wl[ltok] = wlv;
            }
            __syncthreads();   // X (and Wl) ready

            // ---- LDG next stage / next chunk (overlaps compute) ----
            if (s == 0){
                const float4* xr = (const float4*)(xbase + 128 + q*32);
                #pragma unroll
                for (int i = 0; i < 8; i++) xld[i] = xr[i];
            } else if (c + SLICES < nchunks){
                int nc = c + SLICES;
                int tg = nc*CHUNK + ltok;
                int n = g_list_n[bk*NN + (tg < cnt ? tg : nc*CHUNK)];
                wlv = (tg < cnt) ? g_list_w[bk*NN + tg] : 0.f;
                xbase = tokens + (size_t)(b*NN + n)*CC;
                const float4* xr = (const float4*)(xbase + q*32);
                #pragma unroll
                for (int i = 0; i < 8; i++) xld[i] = xr[i];
            }

            // ---- compute: 16 k-tiles; W col block s*128 ----
            const float* Wp = Ws + s*128 + 2*r;
            const float* Xp = sm + (wn*16 + gID)*XSTRIDE + r;
            #pragma unroll 4
            for (int kt = 0; kt < 16; kt++){
                unsigned a[2][4];
                #pragma unroll
                for (int mt = 0; mt < 2; mt++){
                    uint2 lo = *(const uint2*)(Wp + (wm*32 + mt*16 + gID)*WSTRIDE3 + kt*8);
                    uint2 hi = *(const uint2*)(Wp + (wm*32 + mt*16 + gID + 8)*WSTRIDE3 + kt*8);
                    a[mt][0]=lo.x; a[mt][1]=hi.x; a[mt][2]=lo.y; a[mt][3]=hi.y;
                }
                #pragma unroll
                for (int nt = 0; nt < 2; nt++){
                    unsigned b0  = *(const unsigned*)(Xp + nt*8*XSTRIDE + kt*8);
                    unsigned b1v = *(const unsigned*)(Xp + nt*8*XSTRIDE + kt*8 + 4);
                    mma8(acc[0][nt], a[0][0],a[0][1],a[0][2],a[0][3], b0, b1v);
                    mma8(acc[1][nt], a[1][0],a[1][1],a[1][2],a[1][3], b0, b1v);
                }
            }
        }

        // ---- epilogue: bias + relu + wl-weighted accumulate ----
        // D frag: d0=(ch=gID, tok=2r), d1=(gID, 2r+1), d2=(gID+8, 2r), d3=(gID+8, 2r+1)
        #pragma unroll
        for (int mt = 0; mt < 2; mt++)
            #pragma unroll
            for (int nt = 0; nt < 2; nt++){
                int t0 = wn*16 + nt*8 + 2*r;
                float2 wl2 = *(const float2*)(Wl + t0);
                float* d = acc[mt][nt];
                cp[mt][0] += wl2.x*fmaxf(d[0]+bias[mt][0],0.f) + wl2.y*fmaxf(d[1]+bias[mt][0],0.f);
                cp[mt][1] += wl2.x*fmaxf(d[2]+bias[mt][1],0.f) + wl2.y*fmaxf(d[3]+bias[mt][1],0.f);
            }

        c += SLICES;
        if (c >= nchunks) break;
    }

    // ---- reduce over r (fixed butterfly), then across the 4 wn groups via smem ----
    #pragma unroll
    for (int mt = 0; mt < 2; mt++)
        #pragma unroll
        for (int i2 = 0; i2 < 2; i2++){
            float v = cp[mt][i2];
            v += __shfl_xor_sync(0xffffffffu, v, 1);
            v += __shfl_xor_sync(0xffffffffu, v, 2);
            cp[mt][i2] = v;
        }
    __syncthreads();                       // all warps done with X buffer
    if (r == 0){
        #pragma unroll
        for (int mt = 0; mt < 2; mt++)
            #pragma unroll
            for (int i2 = 0; i2 < 2; i2++){
                int ch = wm*32 + mt*16 + i2*8 + gID;
                sm[ch*4 + wn] = cp[mt][i2];
            }
    }
    __syncthreads();
    if (tid < 64){
        g_part[(size_t)(bk*SLICES + sl)*CC + quarter*64 + tid] =
            sm[tid*4] + sm[tid*4 + 1] + sm[tid*4 + 2] + sm[tid*4 + 3];
    }
}

// ---------------- K4: slice reduce + layer-2 GEMM + division ----------------
__global__ void k4_layer2(const float* __restrict__ W2, const float* __restrict__ b2,
                          float* __restrict__ out){
    int bk = blockIdx.x, k = bk & 7;
    int c = threadIdx.x;
    __shared__ __align__(16) float Hs[CC];
    float h = 0.f;
    #pragma unroll
    for (int s = 0; s < SLICES; s++) h += g_part[(size_t)(bk*SLICES + s)*CC + c];
    Hs[c] = h;
    __syncthreads();
    float mass = g_mass[bk];
    float accv = b2[k*CC + c]*mass;
    const float4* w2r = (const float4*)(W2 + (size_t)(k*CC + c)*CC);
    const float4* hr  = (const float4*)Hs;
    #pragma unroll 8
    for (int j = 0; j < 64; j++){
        float4 w = w2r[j]; float4 hh = hr[j];
        accv += w.x*hh.x + w.y*hh.y + w.z*hh.z + w.w*hh.w;
    }
    out[(size_t)bk*CC + c] = accv / fmaxf(mass, EPSF);
}

// ---------------- K5: lb_loss + routing_confidence ----------------
__global__ void k5_final(float* __restrict__ out, int out_size){
    __shared__ float sr[256];
    int tid = threadIdx.x;
    float s = 0.f;
    #pragma unroll 4
    for (int i = 0; i < 32; i++) s += g_confpart[tid*32 + i];
    sr[tid] = s;
    __syncthreads();
    for (int s2 = 128; s2; s2 >>= 1){
        if (tid < s2) sr[tid] += sr[tid + s2];
        __syncthreads();
    }
    if (tid == 0){
        float conf = sr[0] / (float)BN;
        float u[KK]; float mean = 0.f;
        #pragma unroll
        for (int k = 0; k < KK; k++){ u[k] = (float)g_cnt[k] / (float)BN; mean += u[k]; }
        mean /= (float)KK;
        float var = 0.f;
        #pragma unroll
        for (int k = 0; k < KK; k++){ float d = u[k] - mean; var += d*d; }
        var /= (float)KK;
        float stdv = sqrtf(var);
        float ratio = stdv / (mean + EPSF);
        if (out_size > BB*KK*CC)     out[BB*KK*CC]     = ratio*ratio;
        if (out_size > BB*KK*CC + 1) out[BB*KK*CC + 1] = conf;
    }
}

// ---------------- launch ----------------
extern "C" void kernel_launch(void* const* d_in, const int* in_sizes, int n_in,
                              void* d_out, int out_size){
    const float* tokens = (const float*)d_in[0];
    const float* geno   = (const float*)d_in[1];
    const float* Wg     = (const float*)d_in[2];
    const float* bg     = (const float*)d_in[3];
    const float* Wgg    = (const float*)d_in[4];
    const float* bgg    = (const float*)d_in[5];
    const float* W1     = (const float*)d_in[6];
    const float* b1     = (const float*)d_in[7];
    const float* W2     = (const float*)d_in[8];
    const float* b2     = (const float*)d_in[9];
    float* out = (float*)d_out;

    // unconditional every call: deterministic, capture-safe (host attribute set)
    cudaFuncSetAttribute(k3_gemm, cudaFuncAttributeMaxDynamicSharedMemorySize, SM_WORDS*4);

    k0_init   <<<1, 128>>>(geno, Wgg, bgg, bg);
    k1_gate   <<<BN/8, 256>>>(tokens, Wg);
    k2_compact<<<BK, 256>>>();
    k3_gemm   <<<BK*QUARTERS*SLICES, 256, SM_WORDS*4>>>(tokens, W1, b1);
    k4_layer2 <<<BK, 256>>>(W2, b2, out);
    k5_final  <<<1, 256>>>(out, out_size);
}

// round 16
// speedup vs baseline: 1.2036x; 1.2036x over previous
#include <cuda_runtime.h>
#include <math.h>

#define BB 16
#define NN 4096
#define CC 256
#define KK 8
#define SLICES 4
#define CHUNK 64
#define EPSF 1e-6f
#define RATIOF 0.1f

#define BN (BB*NN)   /* 65536 tokens */
#define BK (BB*KK)   /* 128 (batch, expert) pairs */

// ---------------- device scratch (no allocations allowed) ----------------
__device__ float  g_gbias[BK];
__device__ int    g_route_e[BN];      // packed e0 | e1<<8
__device__ float2 g_route_w[BN];      // (w0, w1)
__device__ int    g_cnt[KK];
__device__ float  g_confpart[BN/8];
__device__ int    g_listcnt[BK];
__device__ float  g_mass[BK];
__device__ int    g_list_n[BK*NN];
__device__ float  g_list_w[BK*NN];
__device__ float  g_part[BK*SLICES*CC];

// ---------------- tf32 helpers ----------------
__device__ __forceinline__ unsigned f2tf(float f){
    unsigned u; asm("cvt.rna.tf32.f32 %0, %1;" : "=r"(u) : "f"(f)); return u;
}
__device__ __forceinline__ void mma8(float* d, unsigned a0,unsigned a1,unsigned a2,unsigned a3,
                                     unsigned b0,unsigned b1){
    asm volatile("mma.sync.aligned.m16n8k8.row.col.f32.tf32.tf32.f32 "
                 "{%0,%1,%2,%3}, {%4,%5,%6,%7}, {%8,%9}, {%0,%1,%2,%3};"
                 : "+f"(d[0]), "+f"(d[1]), "+f"(d[2]), "+f"(d[3])
                 : "r"(a0),"r"(a1),"r"(a2),"r"(a3),"r"(b0),"r"(b1));
}

// ---------------- K0: zero counters + per-(b,k) gate bias ----------------
__global__ void k0_init(const float* __restrict__ geno, const float* __restrict__ Wgg,
                        const float* __restrict__ bgg, const float* __restrict__ bg){
    int i = threadIdx.x;              // 0..127 == (b,k)
    if (i < KK) g_cnt[i] = 0;
    int b = i / KK, k = i % KK;
    const float* g = geno + b*CC;
    const float* w = Wgg + k*CC;
    float s = 0.f;
    #pragma unroll 8
    for (int j = 0; j < CC; j++) s += g[j]*w[j];
    g_gbias[i] = bg[k] + RATIOF*(s + bgg[k]);
}

// ---------------- K1: gating (1 warp per token) ----------------
__global__ void k1_gate(const float* __restrict__ tokens, const float* __restrict__ Wg){
    int warp = threadIdx.x >> 5, lane = threadIdx.x & 31;
    int idx = blockIdx.x*8 + warp;
    int b = idx >> 12;
    const float* x = tokens + (size_t)idx*CC;

    float acc[KK];
    #pragma unroll
    for (int k = 0; k < KK; k++) acc[k] = 0.f;
    #pragma unroll
    for (int i = 0; i < 8; i++){
        int j = lane + 32*i;
        float xv = x[j];
        #pragma unroll
        for (int k = 0; k < KK; k++) acc[k] = fmaf(xv, Wg[k*CC + j], acc[k]);
    }
    #pragma unroll
    for (int k = 0; k < KK; k++){
        #pragma unroll
        for (int off = 16; off; off >>= 1) acc[k] += __shfl_xor_sync(0xffffffffu, acc[k], off);
    }

    __shared__ int   s_cnt[KK];
    __shared__ float s_conf[8];
    if (threadIdx.x < KK) s_cnt[threadIdx.x] = 0;
    __syncthreads();

    if (lane == 0){
        float v0 = -1e30f, v1 = -1e30f; int i0 = 0, i1 = 0;
        #pragma unroll
        for (int k = 0; k < KK; k++){
            float v = acc[k] + g_gbias[b*KK + k];
            if (v > v0){ v1 = v0; i1 = i0; v0 = v; i0 = k; }
            else if (v > v1){ v1 = v; i1 = k; }
        }
        float e  = expf(v1 - v0);
        float w0 = 1.f/(1.f + e);
        float w1 = e/(1.f + e);
        w0 = fmaxf(w0, EPSF); w1 = fmaxf(w1, EPSF);
        float inv = 1.f/(w0 + w1); w0 *= inv; w1 *= inv;
        g_route_e[idx] = i0 | (i1 << 8);
        g_route_w[idx] = make_float2(w0, w1);
        atomicAdd(&s_cnt[i0], 1);
        atomicAdd(&s_cnt[i1], 1);
        s_conf[warp] = v0 - v1;
    }
    __syncthreads();
    if (threadIdx.x < KK) atomicAdd(&g_cnt[threadIdx.x], s_cnt[threadIdx.x]);
    if (threadIdx.x == 0){
        float c = 0.f;
        #pragma unroll
        for (int w = 0; w < 8; w++) c += s_conf[w];
        g_confpart[blockIdx.x] = c;
    }
}

// ---------------- K2: deterministic compaction per (b,k) ----------------
__global__ void k2_compact(){
    int bk = blockIdx.x, b = bk >> 3, k = bk & 7;
    int tid = threadIdx.x, lane = tid & 31, warp = tid >> 5;
    __shared__ int   s_base, s_wtot[8], s_woff[8];
    __shared__ float s_wsum[8];
    __shared__ float s_mass;
    if (tid == 0){ s_base = 0; s_mass = 0.f; }
    __syncthreads();

    for (int r = 0; r < 16; r++){
        int t   = r*256 + tid;
        int idx = b*NN + t;
        int pe  = g_route_e[idx];
        float2 ww = g_route_w[idx];
        int e0 = pe & 255, e1 = pe >> 8;
        float myw = (e0 == k) ? ww.x : ((e1 == k) ? ww.y : 0.f);
        int pres = (e0 == k) || (e1 == k);

        unsigned ball = __ballot_sync(0xffffffffu, pres);
        int rank = __popc(ball & ((1u << lane) - 1u));
        float wsum = myw;
        #pragma unroll
        for (int off = 16; off; off >>= 1) wsum += __shfl_xor_sync(0xffffffffu, wsum, off);
        if (lane == 0){ s_wtot[warp] = __popc(ball); s_wsum[warp] = wsum; }
        __syncthreads();
        if (tid == 0){
            int o = s_base; float ms = s_mass;
            #pragma unroll
            for (int w = 0; w < 8; w++){ s_woff[w] = o; o += s_wtot[w]; ms += s_wsum[w]; }
            s_base = o; s_mass = ms;
        }
        __syncthreads();
        if (pres){
            int pos = s_woff[warp] + rank;
            g_list_n[bk*NN + pos] = t;
            g_list_w[bk*NN + pos] = myw;
        }
        __syncthreads();
    }
    if (tid == 0){ g_listcnt[bk] = s_base; g_mass[bk] = s_mass; }
}

// ---------------- K3: tf32 mma.sync layer-1 GEMM (LDS.128 fragments) ----------------
// Per block: 128-channel HALF of W1[k] resident (tf32, 16-col interleave
// pos(m)=4*(m%4)+(m/4), stride 272 => A frags for TWO k-tiles per LDS.128),
// 64-token chunks in two 128-j double-buffered stages (X stride 144, same
// 16-col interleave + per-token position rotation for conflict-free STS).
// Warp tile m32 x n32; register prefetch of next fragment group.
// smem words: Xbuf[2][64tok][144] | Ws[128ch][272] | Wl[2][64]
#define XSTRIDE    144
#define WSTRIDE3   272
#define XBUF_WORDS (64*XSTRIDE)            /* 9216  */
#define WS_OFF     (2*XBUF_WORDS)          /* 18432 */
#define WS_WORDS   (128*WSTRIDE3)          /* 34816 */
#define WL_OFF     (WS_OFF + WS_WORDS)     /* 53248 */
#define SM_WORDS   (WL_OFF + 128)          /* 53376 words = 213504 B */

__global__ void __launch_bounds__(256, 1)
k3_gemm(const float* __restrict__ tokens, const float* __restrict__ W1, const float* __restrict__ b1){
    extern __shared__ float sm[];
    float* Ws = sm + WS_OFF;
    float* Wl = sm + WL_OFF;

    // blockIdx.x = bk*(2*SLICES) + h*SLICES + sl
    int bk   = blockIdx.x >> 3;
    int rest = blockIdx.x & 7;
    int h    = rest >> 2;
    int sl   = rest & 3;
    int b = bk >> 3, k = bk & 7;

    int cnt = g_listcnt[bk];
    int nchunks = (cnt + CHUNK - 1) / CHUNK;

    int tid = threadIdx.x;
    int lane = tid & 31, wid = tid >> 5;
    int gID = lane >> 2, r = lane & 3;
    int wm = wid & 3, wn = wid >> 2;      // wm: 32-channel group, wn: 32-token group

    if (sl >= nchunks){                   // idle slice
        if (tid < 128) g_part[(size_t)(bk*SLICES + sl)*CC + h*128 + tid] = 0.f;
        return;
    }

    // ---- load W1 half [128ch][256j] once: tf32 + 16-col interleave (4x4 transpose) ----
    {
        int row = tid >> 1, p = tid & 1;
        const float* wsrc = W1 + ((size_t)k*CC + h*128 + row)*CC + p*128;
        float* wdst = Ws + row*WSTRIDE3 + p*128;
        #pragma unroll
        for (int g = 0; g < 8; g++){
            float4 fa = *(const float4*)(wsrc + g*16);
            float4 fb = *(const float4*)(wsrc + g*16 + 4);
            float4 fc = *(const float4*)(wsrc + g*16 + 8);
            float4 fd = *(const float4*)(wsrc + g*16 + 12);
            uint4 u0 = {f2tf(fa.x), f2tf(fb.x), f2tf(fc.x), f2tf(fd.x)};
            uint4 u1 = {f2tf(fa.y), f2tf(fb.y), f2tf(fc.y), f2tf(fd.y)};
            uint4 u2 = {f2tf(fa.z), f2tf(fb.z), f2tf(fc.z), f2tf(fd.z)};
            uint4 u3 = {f2tf(fa.w), f2tf(fb.w), f2tf(fc.w), f2tf(fd.w)};
            *(uint4*)(wdst + g*16 + 0)  = u0;
            *(uint4*)(wdst + g*16 + 4)  = u1;
            *(uint4*)(wdst + g*16 + 8)  = u2;
            *(uint4*)(wdst + g*16 + 12) = u3;
        }
    }

    // bias: channels wm*32 + mt*16 + gID (+8)
    float bias[2][2];
    {
        const float* bp = b1 + k*CC + h*128 + wm*32;
        bias[0][0] = bp[gID];      bias[0][1] = bp[gID + 8];
        bias[1][0] = bp[16 + gID]; bias[1][1] = bp[24 + gID];
    }

    float cp[2][2] = {{0.f,0.f},{0.f,0.f}};

    // loader: token ltok (0..63), j-quarter q (32 j of the 128-j stage)
    int ltok = tid & 63, q = tid >> 6;
    int srot = (ltok >> 1) & 3;                       // STS position rotation
    int pos_b = ((r + ((gID >> 1) & 3)) & 3) * 4;     // matching B-load position (per-thread const)

    // prologue: chunk sl, row lookup + wl + LDG stage0 (j 0..127)
    int c = sl;
    const float* xbase;
    float wlv;
    float4 xld[8];
    {
        int tg = c*CHUNK + ltok;
        int n = g_list_n[bk*NN + (tg < cnt ? tg : c*CHUNK)];
        wlv = (tg < cnt) ? g_list_w[bk*NN + tg] : 0.f;
        xbase = tokens + (size_t)(b*NN + n)*CC;
        const float4* xr = (const float4*)(xbase + q*32);
        #pragma unroll
        for (int i = 0; i < 8; i++) xld[i] = xr[i];
    }

    int ord = 0;
    while (1){
        int par = ord & 1;
        float acc[2][4][4];
        #pragma unroll
        for (int mt=0; mt<2; mt++)
            #pragma unroll
            for (int nt=0; nt<4; nt++)
                #pragma unroll
                for (int i2=0; i2<4; i2++) acc[mt][nt][i2] = 0.f;

        #pragma unroll
        for (int s = 0; s < 2; s++){
            float* Xb = sm + s*XBUF_WORDS;
            // ---- STS stage s: tf32 + 16-col interleave transpose + rotated positions ----
            {
                float* xd = Xb + ltok*XSTRIDE + q*32;
                #pragma unroll
                for (int g = 0; g < 2; g++){
                    const float4* xs = &xld[g*4];
                    uint4 u0 = {f2tf(xs[0].x), f2tf(xs[1].x), f2tf(xs[2].x), f2tf(xs[3].x)};
                    uint4 u1 = {f2tf(xs[0].y), f2tf(xs[1].y), f2tf(xs[2].y), f2tf(xs[3].y)};
                    uint4 u2 = {f2tf(xs[0].z), f2tf(xs[1].z), f2tf(xs[2].z), f2tf(xs[3].z)};
                    uint4 u3 = {f2tf(xs[0].w), f2tf(xs[1].w), f2tf(xs[2].w), f2tf(xs[3].w)};
                    *(uint4*)(xd + g*16 + (((0+srot)&3)<<2)) = u0;
                    *(uint4*)(xd + g*16 + (((1+srot)&3)<<2)) = u1;
                    *(uint4*)(xd + g*16 + (((2+srot)&3)<<2)) = u2;
                    *(uint4*)(xd + g*16 + (((3+srot)&3)<<2)) = u3;
                }
                if (s == 0 && q == 0) Wl[par*64 + ltok] = wlv;
            }
            __syncthreads();   // stage ready; depth-2 buffer safe (program-order proof)

            // ---- LDG next (overlaps compute) ----
            if (s == 0){
                const float4* xr = (const float4*)(xbase + 128 + q*32);
                #pragma unroll
                for (int i = 0; i < 8; i++) xld[i] = xr[i];
            } else if (c + SLICES < nchunks){
                int nc = c + SLICES;
                int tg = nc*CHUNK + ltok;
                int n = g_list_n[bk*NN + (tg < cnt ? tg : nc*CHUNK)];
                wlv = (tg < cnt) ? g_list_w[bk*NN + tg] : 0.f;
                xbase = tokens + (size_t)(b*NN + n)*CC;
                const float4* xr = (const float4*)(xbase + q*32);
                #pragma unroll
                for (int i = 0; i < 8; i++) xld[i] = xr[i];
            }

            // ---- compute: 8 groups of 2 k-tiles; LDS.128 frags + prefetch ----
            {
                const float* WpA0 = Ws + s*128 + (wm*32 + gID)*WSTRIDE3 + 4*r;
                const float* WpA1 = Ws + s*128 + (wm*32 + 16 + gID)*WSTRIDE3 + 4*r;
                const float* XpB  = Xb + (wn*32 + gID)*XSTRIDE + pos_b;

                uint4 fa[2][2], fb[4];
                fa[0][0] = *(const uint4*)(WpA0);
                fa[0][1] = *(const uint4*)(WpA0 + 8*WSTRIDE3);
                fa[1][0] = *(const uint4*)(WpA1);
                fa[1][1] = *(const uint4*)(WpA1 + 8*WSTRIDE3);
                #pragma unroll
                for (int nt = 0; nt < 4; nt++)
                    fb[nt] = *(const uint4*)(XpB + nt*8*XSTRIDE);

                #pragma unroll
                for (int grp = 0; grp < 8; grp++){
                    uint4 na[2][2], nb[4];
                    if (grp < 7){
                        int off = (grp+1)*16;
                        na[0][0] = *(const uint4*)(WpA0 + off);
                        na[0][1] = *(const uint4*)(WpA0 + 8*WSTRIDE3 + off);
                        na[1][0] = *(const uint4*)(WpA1 + off);
                        na[1][1] = *(const uint4*)(WpA1 + 8*WSTRIDE3 + off);
                        #pragma unroll
                        for (int nt = 0; nt < 4; nt++)
                            nb[nt] = *(const uint4*)(XpB + nt*8*XSTRIDE + off);
                    }
                    #pragma unroll
                    for (int mt = 0; mt < 2; mt++)
                        #pragma unroll
                        for (int nt = 0; nt < 4; nt++){
                            mma8(acc[mt][nt], fa[mt][0].x, fa[mt][1].x, fa[mt][0].y, fa[mt][1].y,
                                 fb[nt].x, fb[nt].y);
                            mma8(acc[mt][nt], fa[mt][0].z, fa[mt][1].z, fa[mt][0].w, fa[mt][1].w,
                                 fb[nt].z, fb[nt].w);
                        }
                    if (grp < 7){
                        #pragma unroll
                        for (int mt = 0; mt < 2; mt++){ fa[mt][0] = na[mt][0]; fa[mt][1] = na[mt][1]; }
                        #pragma unroll
                        for (int nt = 0; nt < 4; nt++) fb[nt] = nb[nt];
                    }
                }
            }
        }

        // ---- epilogue: bias + relu + wl-weighted accumulate ----
        // D frag: d0=(ch=gID, tok=2r), d1=(gID, 2r+1), d2=(gID+8, 2r), d3=(gID+8, 2r+1)
        #pragma unroll
        for (int mt = 0; mt < 2; mt++)
            #pragma unroll
            for (int nt = 0; nt < 4; nt++){
                int t0 = wn*32 + nt*8 + 2*r;
                float2 wl2 = *(const float2*)(Wl + par*64 + t0);
                float* d = acc[mt][nt];
                cp[mt][0] += wl2.x*fmaxf(d[0]+bias[mt][0],0.f) + wl2.y*fmaxf(d[1]+bias[mt][0],0.f);
                cp[mt][1] += wl2.x*fmaxf(d[2]+bias[mt][1],0.f) + wl2.y*fmaxf(d[3]+bias[mt][1],0.f);
            }

        c += SLICES; ord++;
        if (c >= nchunks) break;
    }

    // ---- reduce over r (fixed butterfly), then across wn pairs via smem ----
    #pragma unroll
    for (int mt = 0; mt < 2; mt++)
        #pragma unroll
        for (int i2 = 0; i2 < 2; i2++){
            float v = cp[mt][i2];
            v += __shfl_xor_sync(0xffffffffu, v, 1);
            v += __shfl_xor_sync(0xffffffffu, v, 2);
            cp[mt][i2] = v;
        }
    __syncthreads();                       // all warps done with X buffers
    if (r == 0){
        #pragma unroll
        for (int mt = 0; mt < 2; mt++)
            #pragma unroll
            for (int i2 = 0; i2 < 2; i2++){
                int ch = wm*32 + mt*16 + i2*8 + gID;
                sm[ch*2 + wn] = cp[mt][i2];
            }
    }
    __syncthreads();
    if (tid < 128){
        g_part[(size_t)(bk*SLICES + sl)*CC + h*128 + tid] = sm[tid*2] + sm[tid*2 + 1];
    }
}

// ---------------- K4: slice reduce + layer-2 GEMM + division ----------------
__global__ void k4_layer2(const float* __restrict__ W2, const float* __restrict__ b2,
                          float* __restrict__ out){
    int bk = blockIdx.x, k = bk & 7;
    int c = threadIdx.x;
    __shared__ __align__(16) float Hs[CC];
    float h = 0.f;
    #pragma unroll
    for (int s = 0; s < SLICES; s++) h += g_part[(size_t)(bk*SLICES + s)*CC + c];
    Hs[c] = h;
    __syncthreads();
    float mass = g_mass[bk];
    float accv = b2[k*CC + c]*mass;
    const float4* w2r = (const float4*)(W2 + (size_t)(k*CC + c)*CC);
    const float4* hr  = (const float4*)Hs;
    #pragma unroll 8
    for (int j = 0; j < 64; j++){
        float4 w = w2r[j]; float4 hh = hr[j];
        accv += w.x*hh.x + w.y*hh.y + w.z*hh.z + w.w*hh.w;
    }
    out[(size_t)bk*CC + c] = accv / fmaxf(mass, EPSF);
}

// ---------------- K5: lb_loss + routing_confidence ----------------
__global__ void k5_final(float* __restrict__ out, int out_size){
    __shared__ float sr[256];
    int tid = threadIdx.x;
    float s = 0.f;
    #pragma unroll 4
    for (int i = 0; i < 32; i++) s += g_confpart[tid*32 + i];
    sr[tid] = s;
    __syncthreads();
    for (int s2 = 128; s2; s2 >>= 1){
        if (tid < s2) sr[tid] += sr[tid + s2];
        __syncthreads();
    }
    if (tid == 0){
        float conf = sr[0] / (float)BN;
        float u[KK]; float mean = 0.f;
        #pragma unroll
        for (int k = 0; k < KK; k++){ u[k] = (float)g_cnt[k] / (float)BN; mean += u[k]; }
        mean /= (float)KK;
        float var = 0.f;
        #pragma unroll
        for (int k = 0; k < KK; k++){ float d = u[k] - mean; var += d*d; }
        var /= (float)KK;
        float stdv = sqrtf(var);
        float ratio = stdv / (mean + EPSF);
        if (out_size > BB*KK*CC)     out[BB*KK*CC]     = ratio*ratio;
        if (out_size > BB*KK*CC + 1) out[BB*KK*CC + 1] = conf;
    }
}

// ---------------- launch ----------------
extern "C" void kernel_launch(void* const* d_in, const int* in_sizes, int n_in,
                              void* d_out, int out_size){
    const float* tokens = (const float*)d_in[0];
    const float* geno   = (const float*)d_in[1];
    const float* Wg     = (const float*)d_in[2];
    const float* bg     = (const float*)d_in[3];
    const float* Wgg    = (const float*)d_in[4];
    const float* bgg    = (const float*)d_in[5];
    const float* W1     = (const float*)d_in[6];
    const float* b1     = (const float*)d_in[7];
    const float* W2     = (const float*)d_in[8];
    const float* b2     = (const float*)d_in[9];
    float* out = (float*)d_out;

    // unconditional every call: deterministic, capture-safe (host attribute set)
    cudaFuncSetAttribute(k3_gemm, cudaFuncAttributeMaxDynamicSharedMemorySize, SM_WORDS*4);

    k0_init   <<<1, 128>>>(geno, Wgg, bgg, bg);
    k1_gate   <<<BN/8, 256>>>(tokens, Wg);
    k2_compact<<<BK, 256>>>();
    k3_gemm   <<<BK*2*SLICES, 256, SM_WORDS*4>>>(tokens, W1, b1);
    k4_layer2 <<<BK, 256>>>(W2, b2, out);
    k5_final  <<<1, 256>>>(out, out_size);
}